// round 4
// baseline (speedup 1.0000x reference)
#include <cuda_runtime.h>

// ButterflyLinear: 12 butterfly stages on N=4096, TOKENS=8192.
// Stage 0 pairs (j, j^1); stages 1..11 all pair (j, j^2) => transform is
// block-diagonal in 4-element groups. Precompute 4x4 per-group matrix A_g
// (column-major), then out = blockdiag(A) * x + bias (pure streaming).
// The two kernels are overlapped with PDL: apply launches concurrently,
// prefetches x, and grid-dependency-syncs only before reading g_C.

#define TOKENS 8192
#define NCOLS  4096
#define DEPTH  12
#define GROUPS (NCOLS / 4)   // 1024
#define PAIRS  (NCOLS / 2)   // 2048 factor pairs per stage
#define T_PER  16            // tokens per thread in apply kernel

// Scratch: 1024 groups x 4 columns (each column = float4) = 64 KB.
// g_C[g*4+e] = (A[0][e], A[1][e], A[2][e], A[3][e])
__device__ float4 g_C[GROUPS * 4];

// ---------------------------------------------------------------------------
// Kernel 1: fold 12 stage matrices into one 4x4 per group, one thread per
// (group, column); column-separable recurrence, front-batched MLP=24 loads.
// Triggers programmatic launch completion immediately so the dependent
// apply kernel can begin launching/prefetching while this runs.
// factors layout: F[stage][pair][c][d] as float4 per pair:
//   f.x=f[0][0], f.y=f[0][1], f.z=f[1][0], f.w=f[1][1]
// Stage semantics: y[d] = sum_c pair_in[c] * f[c][d]
// ---------------------------------------------------------------------------
__global__ void butterfly_precompute(const float4* __restrict__ F4) {
#if __CUDA_ARCH__ >= 900
    cudaTriggerProgrammaticLaunchCompletion();
#endif
    int t = blockIdx.x * blockDim.x + threadIdx.x;   // 0..4095
    int g = t >> 2;
    int e = t & 3;
    int j0 = 4 * g;

    // ---- front-batched loads: 24 independent float4 LDGs ----
    float4 fa[DEPTH], fb[DEPTH];
    fa[0] = F4[2 * g];
    fb[0] = F4[2 * g + 1];
    #pragma unroll
    for (int s = 1; s < DEPTH; s++) {
        int block = 1 << (s + 1);
        int pA = ((j0 >> (s + 1)) << s) | ((j0 & (block - 1)) >> 2);
        int pB = pA + (1 << (s - 1));
        fa[s] = F4[s * PAIRS + pA];
        fb[s] = F4[s * PAIRS + pB];
    }

    // ---- stage-0 initial column e of A ----
    float A0, A1, A2, A3;
    {
        float4 f0 = fa[0], f1 = fb[0];
        bool lo = (e < 2);
        float4 f = lo ? f0 : f1;
        float u = (e & 1) ? f.z : f.x;
        float v = (e & 1) ? f.w : f.y;
        A0 = lo ? u : 0.f;
        A1 = lo ? v : 0.f;
        A2 = lo ? 0.f : u;
        A3 = lo ? 0.f : v;
    }

    // ---- fold stages 1..11 on this column ----
    #pragma unroll
    for (int s = 1; s < DEPTH; s++) {
        float a00 = fa[s].x, a01 = fa[s].y, a10 = fa[s].z, a11 = fa[s].w;
        float b00 = fb[s].x, b01 = fb[s].y, b10 = fb[s].z, b11 = fb[s].w;
        float r0 = A0, r1 = A1, r2 = A2, r3 = A3;
        A0 = a00 * r0 + a10 * r2;
        A2 = a01 * r0 + a11 * r2;
        A1 = b00 * r1 + b10 * r3;
        A3 = b01 * r1 + b11 * r3;
    }

    g_C[t] = make_float4(A0, A1, A2, A3);
}

// ---------------------------------------------------------------------------
// Kernel 2: out[t, group g] = A_g * x[t, g] + bias_g (column-major A).
// Prefetches the first 4 token-chunks and bias BEFORE the grid dependency
// sync, so precompute's tail is hidden under our first DRAM round-trip.
// ---------------------------------------------------------------------------
__global__ void __launch_bounds__(256)
butterfly_apply(const float4* __restrict__ x,
                const float4* __restrict__ bias4,
                float4* __restrict__ out) {
    int g  = blockIdx.x * blockDim.x + threadIdx.x;  // 0..GROUPS-1
    int t0 = blockIdx.y * T_PER;

    const float4* xp = x   + (size_t)t0 * GROUPS + g;
    float4*       op = out + (size_t)t0 * GROUPS + g;

    // ---- independent prefetches (legal before the dependency sync) ----
    float4 v0 = __ldcs(xp + 0 * GROUPS);
    float4 v1 = __ldcs(xp + 1 * GROUPS);
    float4 v2 = __ldcs(xp + 2 * GROUPS);
    float4 v3 = __ldcs(xp + 3 * GROUPS);
    float4 b  = bias4[g];

#if __CUDA_ARCH__ >= 900
    cudaGridDependencySynchronize();   // wait for precompute's g_C writes
#endif

    float4 c0 = g_C[g * 4 + 0];
    float4 c1 = g_C[g * 4 + 1];
    float4 c2 = g_C[g * 4 + 2];
    float4 c3 = g_C[g * 4 + 3];

    #pragma unroll
    for (int ii = 0; ii < T_PER; ii += 4) {
        float4 r0, r1, r2, r3;
        r0.x = b.x + v0.x*c0.x + v0.y*c1.x + v0.z*c2.x + v0.w*c3.x;
        r0.y = b.y + v0.x*c0.y + v0.y*c1.y + v0.z*c2.y + v0.w*c3.y;
        r0.z = b.z + v0.x*c0.z + v0.y*c1.z + v0.z*c2.z + v0.w*c3.z;
        r0.w = b.w + v0.x*c0.w + v0.y*c1.w + v0.z*c2.w + v0.w*c3.w;

        r1.x = b.x + v1.x*c0.x + v1.y*c1.x + v1.z*c2.x + v1.w*c3.x;
        r1.y = b.y + v1.x*c0.y + v1.y*c1.y + v1.z*c2.y + v1.w*c3.y;
        r1.z = b.z + v1.x*c0.z + v1.y*c1.z + v1.z*c2.z + v1.w*c3.z;
        r1.w = b.w + v1.x*c0.w + v1.y*c1.w + v1.z*c2.w + v1.w*c3.w;

        r2.x = b.x + v2.x*c0.x + v2.y*c1.x + v2.z*c2.x + v2.w*c3.x;
        r2.y = b.y + v2.x*c0.y + v2.y*c1.y + v2.z*c2.y + v2.w*c3.y;
        r2.z = b.z + v2.x*c0.z + v2.y*c1.z + v2.z*c2.z + v2.w*c3.z;
        r2.w = b.w + v2.x*c0.w + v2.y*c1.w + v2.z*c2.w + v2.w*c3.w;

        r3.x = b.x + v3.x*c0.x + v3.y*c1.x + v3.z*c2.x + v3.w*c3.x;
        r3.y = b.y + v3.x*c0.y + v3.y*c1.y + v3.z*c2.y + v3.w*c3.y;
        r3.z = b.z + v3.x*c0.z + v3.y*c1.z + v3.z*c2.z + v3.w*c3.z;
        r3.w = b.w + v3.x*c0.w + v3.y*c1.w + v3.z*c2.w + v3.w*c3.w;

        // issue next chunk's loads before the stores so they're in flight
        if (ii + 4 < T_PER) {
            v0 = __ldcs(xp + (size_t)(ii + 4) * GROUPS);
            v1 = __ldcs(xp + (size_t)(ii + 5) * GROUPS);
            v2 = __ldcs(xp + (size_t)(ii + 6) * GROUPS);
            v3 = __ldcs(xp + (size_t)(ii + 7) * GROUPS);
        }

        __stcs(op + (size_t)(ii + 0) * GROUPS, r0);
        __stcs(op + (size_t)(ii + 1) * GROUPS, r1);
        __stcs(op + (size_t)(ii + 2) * GROUPS, r2);
        __stcs(op + (size_t)(ii + 3) * GROUPS, r3);
    }
}

// ---------------------------------------------------------------------------
extern "C" void kernel_launch(void* const* d_in, const int* in_sizes, int n_in,
                              void* d_out, int out_size) {
    const float* x = nullptr;
    const float* factors = nullptr;
    const float* bias = nullptr;
    for (int i = 0; i < n_in; i++) {
        if (in_sizes[i] == TOKENS * NCOLS)            x = (const float*)d_in[i];
        else if (in_sizes[i] == DEPTH * PAIRS * 4)    factors = (const float*)d_in[i];
        else if (in_sizes[i] == NCOLS)                bias = (const float*)d_in[i];
    }

    // Kernel 1: 4096 threads = 1 per (group, column).
    butterfly_precompute<<<32, 128>>>((const float4*)factors);

    // Kernel 2 with programmatic stream serialization (PDL): launches while
    // precompute is still running; device-side sync guards the g_C reads.
    cudaLaunchConfig_t cfg = {};
    cfg.gridDim  = dim3(GROUPS / 256, TOKENS / T_PER);
    cfg.blockDim = dim3(256);
    cfg.dynamicSmemBytes = 0;
    cfg.stream = 0;
    cudaLaunchAttribute attrs[1];
    attrs[0].id = cudaLaunchAttributeProgrammaticStreamSerialization;
    attrs[0].val.programmaticStreamSerializationAllowed = 1;
    cfg.attrs = attrs;
    cfg.numAttrs = 1;

    cudaLaunchKernelEx(&cfg, butterfly_apply,
                       (const float4*)x, (const float4*)bias, (float4*)d_out);
}